// round 1
// baseline (speedup 1.0000x reference)
#include <cuda_runtime.h>
#include <cuda_bf16.h>
#include <cstdint>

#define BATCH 8192
#define DFEAT 784
#define KPAD  800
#define KT    25          // KPAD / 32 k-tiles

// bf16 normalized features scratch, K padded to 800 with zeros
__device__ __nv_bfloat16 g_qn[(size_t)BATCH * KPAD];

// ---------------------------------------------------------------------------
// Kernel A: conv(2x2,s2)+bias -> flatten -> groupwise 4x4 unitary -> qf
//           -> row norm -> bf16 qn scratch; linear head -> log_softmax
// One block per image, 256 threads.
// ---------------------------------------------------------------------------
__global__ __launch_bounds__(256) void prep_kernel(
    const float* __restrict__ x, const float* __restrict__ conv_w,
    const float* __restrict__ conv_b, const float* __restrict__ unitary,
    const float* __restrict__ lin_w, const float* __restrict__ lin_b,
    float* __restrict__ out_logp)
{
    __shared__ float xs[784];
    __shared__ float flat[784];
    __shared__ float qf[784];
    __shared__ float cw[16];
    __shared__ float cb[4];
    __shared__ float U[16];
    __shared__ float ssw[8];
    __shared__ float wred[8][10];
    __shared__ float sinv;

    const int b = blockIdx.x;
    const int tid = threadIdx.x;
    const int lane = tid & 31;
    const int wid = tid >> 5;

    if (tid < 16)                cw[tid]      = conv_w[tid];
    if (tid >= 32 && tid < 36)   cb[tid - 32] = conv_b[tid - 32];
    if (tid >= 64 && tid < 80)   U[tid - 64]  = unitary[tid - 64];

    const float* xb = x + (size_t)b * 784;
    for (int i = tid; i < 784; i += 256) xs[i] = xb[i];
    __syncthreads();

    // conv 2x2 stride 2: flat[o*196 + i*14 + j]
    for (int idx = tid; idx < 784; idx += 256) {
        int o = idx / 196;
        int p = idx - o * 196;
        int i = p / 14;
        int j = p - i * 14;
        const float* xr = xs + (2 * i) * 28 + 2 * j;
        flat[idx] = cb[o] + cw[o*4+0]*xr[0]  + cw[o*4+1]*xr[1]
                          + cw[o*4+2]*xr[28] + cw[o*4+3]*xr[29];
    }
    __syncthreads();

    // groups of 4 consecutive flat values through unitary^T; accumulate sumsq
    float ss = 0.f;
    for (int idx = tid; idx < 784; idx += 256) {
        int n4 = idx & ~3;
        int w  = idx & 3;
        float v = flat[n4+0]*U[w*4+0] + flat[n4+1]*U[w*4+1]
                + flat[n4+2]*U[w*4+2] + flat[n4+3]*U[w*4+3];
        qf[idx] = v;
        ss += v * v;
    }
#pragma unroll
    for (int o = 16; o; o >>= 1) ss += __shfl_xor_sync(0xffffffffu, ss, o);
    if (lane == 0) ssw[wid] = ss;
    __syncthreads();
    if (tid == 0) {
        float t = 0.f;
#pragma unroll
        for (int i = 0; i < 8; i++) t += ssw[i];
        sinv = 1.f / (sqrtf(t) + 1e-12f);
    }
    __syncthreads();
    const float inv = sinv;

    // write bf16 normalized features (padded K)
    for (int idx = tid; idx < 784; idx += 256)
        g_qn[(size_t)b * KPAD + idx] = __float2bfloat16(qf[idx] * inv);
    if (tid < KPAD - 784)
        g_qn[(size_t)b * KPAD + 784 + tid] = __float2bfloat16(0.f);

    // linear head: 10 dot products over 784
    float part[10];
#pragma unroll
    for (int c = 0; c < 10; c++) part[c] = 0.f;
    for (int d = tid; d < 784; d += 256) {
        float v = qf[d];
#pragma unroll
        for (int c = 0; c < 10; c++) part[c] += v * lin_w[c * 784 + d];
    }
#pragma unroll
    for (int c = 0; c < 10; c++) {
        float v = part[c];
#pragma unroll
        for (int o = 16; o; o >>= 1) v += __shfl_xor_sync(0xffffffffu, v, o);
        if (lane == 0) wred[wid][c] = v;
    }
    __syncthreads();
    if (tid == 0) {
        float lg[10];
#pragma unroll
        for (int c = 0; c < 10; c++) {
            float t = lin_b[c];
#pragma unroll
            for (int w8 = 0; w8 < 8; w8++) t += wred[w8][c];
            lg[c] = t;
        }
        float mx = lg[0];
#pragma unroll
        for (int c = 1; c < 10; c++) mx = fmaxf(mx, lg[c]);
        float s = 0.f;
#pragma unroll
        for (int c = 0; c < 10; c++) s += expf(lg[c] - mx);
        float lse = mx + logf(s);
#pragma unroll
        for (int c = 0; c < 10; c++) out_logp[(size_t)b * 10 + c] = lg[c] - lse;
    }
}

// ---------------------------------------------------------------------------
// Kernel B: adj = ((qn qn^T)^2 >= 0.9) & (i != j), symmetric.
// bf16 mma.sync m16n8k16; 128x128x32 block tiles; cp.async double buffer;
// only upper-triangular block tiles computed, mirror-written.
// ---------------------------------------------------------------------------
__device__ __forceinline__ void ldsm4(uint32_t& r0, uint32_t& r1,
                                      uint32_t& r2, uint32_t& r3, uint32_t addr)
{
    asm volatile("ldmatrix.sync.aligned.m8n8.x4.shared.b16 {%0,%1,%2,%3}, [%4];"
                 : "=r"(r0), "=r"(r1), "=r"(r2), "=r"(r3) : "r"(addr));
}

__device__ __forceinline__ void mma16816(float* c, const uint32_t* a, const uint32_t* b)
{
    asm volatile("mma.sync.aligned.m16n8k16.row.col.f32.bf16.bf16.f32 "
                 "{%0,%1,%2,%3}, {%4,%5,%6,%7}, {%8,%9}, {%0,%1,%2,%3};"
                 : "+f"(c[0]), "+f"(c[1]), "+f"(c[2]), "+f"(c[3])
                 : "r"(a[0]), "r"(a[1]), "r"(a[2]), "r"(a[3]),
                   "r"(b[0]), "r"(b[1]));
}

__global__ __launch_bounds__(256) void adj_kernel(float* __restrict__ adj)
{
    const int bc = blockIdx.x;
    const int br = blockIdx.y;
    if (br > bc) return;   // symmetry: compute upper-triangular tiles only

    __shared__ __align__(16) __nv_bfloat16 As[2][128 * 32];
    __shared__ __align__(16) __nv_bfloat16 Bs[2][128 * 32];

    const int tid  = threadIdx.x;
    const int lane = tid & 31;
    const int wid  = tid >> 5;
    const int wm   = wid >> 2;   // 0..1  (64 rows each)
    const int wn   = wid & 3;    // 0..3  (32 cols each)

    const uint32_t aBase = (uint32_t)__cvta_generic_to_shared(&As[0][0]);
    const uint32_t bBase = (uint32_t)__cvta_generic_to_shared(&Bs[0][0]);

    float acc[4][4][4];
#pragma unroll
    for (int i = 0; i < 4; i++)
#pragma unroll
        for (int j = 0; j < 4; j++)
#pragma unroll
            for (int k = 0; k < 4; k++) acc[i][j][k] = 0.f;

    const __nv_bfloat16* gA = g_qn + (size_t)br * 128 * KPAD;
    const __nv_bfloat16* gB = g_qn + (size_t)bc * 128 * KPAD;

    auto load_tile = [&](int buf, int k0) {
#pragma unroll
        for (int t = 0; t < 2; ++t) {
            int idx = tid + t * 256;
            int row = idx >> 2;
            int ch  = idx & 3;
            int sw  = ch ^ ((row >> 1) & 3);
            uint32_t soff = (uint32_t)((buf * 4096 + row * 32 + sw * 8) * 2);
            const __nv_bfloat16* ga = gA + (size_t)row * KPAD + k0 + ch * 8;
            const __nv_bfloat16* gb = gB + (size_t)row * KPAD + k0 + ch * 8;
            uint32_t sa = aBase + soff;
            uint32_t sb = bBase + soff;
            asm volatile("cp.async.cg.shared.global [%0], [%1], 16;" :: "r"(sa), "l"(ga));
            asm volatile("cp.async.cg.shared.global [%0], [%1], 16;" :: "r"(sb), "l"(gb));
        }
    };

    auto compute = [&](int buf) {
        const uint32_t base_a = aBase + buf * 8192;
        const uint32_t base_b = bBase + buf * 8192;
#pragma unroll
        for (int ks = 0; ks < 32; ks += 16) {
            uint32_t a[4][4], bb[4][2];
#pragma unroll
            for (int mf = 0; mf < 4; ++mf) {
                int row = wm * 64 + mf * 16 + (lane & 15);
                int col = ks + ((lane >> 4) << 3);
                int ch  = (col >> 3) ^ ((row >> 1) & 3);
                uint32_t addr = base_a + (uint32_t)((row * 32 + ch * 8) * 2);
                ldsm4(a[mf][0], a[mf][1], a[mf][2], a[mf][3], addr);
            }
#pragma unroll
            for (int nf2 = 0; nf2 < 2; ++nf2) {
                int row = wn * 32 + nf2 * 16 + ((lane >> 4) << 3) + (lane & 7);
                int col = ks + ((lane >> 3) & 1) * 8;
                int ch  = (col >> 3) ^ ((row >> 1) & 3);
                uint32_t addr = base_b + (uint32_t)((row * 32 + ch * 8) * 2);
                ldsm4(bb[nf2*2][0], bb[nf2*2][1], bb[nf2*2+1][0], bb[nf2*2+1][1], addr);
            }
#pragma unroll
            for (int mf = 0; mf < 4; ++mf)
#pragma unroll
                for (int nf = 0; nf < 4; ++nf)
                    mma16816(acc[mf][nf], a[mf], bb[nf]);
        }
    };

    load_tile(0, 0);
    asm volatile("cp.async.commit_group;");
#pragma unroll 1
    for (int kt = 0; kt < KT; ++kt) {
        if (kt + 1 < KT) {
            load_tile((kt + 1) & 1, (kt + 1) * 32);
            asm volatile("cp.async.commit_group;");
            asm volatile("cp.async.wait_group 1;");
        } else {
            asm volatile("cp.async.wait_group 0;");
        }
        __syncthreads();
        compute(kt & 1);
        __syncthreads();
    }

    // epilogue: fid = c^2, threshold 0.9, no self edges; mirror for br<bc
    const int g   = lane >> 2;
    const int tig = lane & 3;
#pragma unroll
    for (int mf = 0; mf < 4; ++mf) {
        int r0 = br * 128 + wm * 64 + mf * 16 + g;
#pragma unroll
        for (int nf = 0; nf < 4; ++nf) {
            int c0 = bc * 128 + wn * 32 + nf * 8 + tig * 2;
            float f0 = acc[mf][nf][0], f1 = acc[mf][nf][1];
            float f2 = acc[mf][nf][2], f3 = acc[mf][nf][3];
            float v0 = (f0 * f0 >= 0.9f && r0     != c0    ) ? 1.f : 0.f;
            float v1 = (f1 * f1 >= 0.9f && r0     != c0 + 1) ? 1.f : 0.f;
            float v2 = (f2 * f2 >= 0.9f && r0 + 8 != c0    ) ? 1.f : 0.f;
            float v3 = (f3 * f3 >= 0.9f && r0 + 8 != c0 + 1) ? 1.f : 0.f;
            float2 p0 = make_float2(v0, v1);
            float2 p1 = make_float2(v2, v3);
            *reinterpret_cast<float2*>(&adj[(size_t)r0 * BATCH + c0])       = p0;
            *reinterpret_cast<float2*>(&adj[(size_t)(r0 + 8) * BATCH + c0]) = p1;
            if (br != bc) {
                adj[(size_t)c0       * BATCH + r0]     = v0;
                adj[(size_t)(c0 + 1) * BATCH + r0]     = v1;
                adj[(size_t)c0       * BATCH + r0 + 8] = v2;
                adj[(size_t)(c0 + 1) * BATCH + r0 + 8] = v3;
            }
        }
    }
}

// ---------------------------------------------------------------------------
extern "C" void kernel_launch(void* const* d_in, const int* in_sizes, int n_in,
                              void* d_out, int out_size)
{
    const float* x       = (const float*)d_in[0];
    const float* conv_w  = (const float*)d_in[1];
    const float* conv_b  = (const float*)d_in[2];
    const float* unitary = (const float*)d_in[3];
    const float* lin_w   = (const float*)d_in[4];
    const float* lin_b   = (const float*)d_in[5];
    float* out = (float*)d_out;

    prep_kernel<<<BATCH, 256>>>(x, conv_w, conv_b, unitary, lin_w, lin_b, out);

    dim3 grid(BATCH / 128, BATCH / 128);
    adj_kernel<<<grid, 256>>>(out + (size_t)BATCH * 10);
}